// round 13
// baseline (speedup 1.0000x reference)
#include <cuda_runtime.h>
#include <cuda_bf16.h>
#include <cstdint>

// ===========================================================================
#define LDA0 3264            // 3201 padded to /64 (bf16 elems)

// float-offset layout (g_buf zero-initialized at load; pad regions never
// written -> statically zero across all calls)
#define O_A1   0ULL            // bf16 [8000*3264]
#define O_A2   13056000ULL     // bf16 [8000*1024] (also layers 3/4 with ld 512)
#define O_XL   17152000ULL     // bf16 8000*1024 (f32-sized slot, half used)
#define O_XR   25344000ULL     // bf16 8000*1024
#define O_H1   33536000ULL     // f32 8000*1024
#define O_H2   41728000ULL     // f32 8000*512
#define O_H3   45824000ULL     // f32 8000*512
#define O_H4   49920000ULL     // f32 8000*512
#define O_BT1  54016000ULL     // bf16 2048*3264
#define O_BT2  57358336ULL     // bf16 1024*1024
#define O_BT3  57882624ULL     // bf16 1024*512
#define O_BT4  58144768ULL     // bf16 1024*512
#define O_STAT 58406912ULL     // per-layer SUM/SQ: L1 2*3264, L2 2*1024, L3/L4 2*512
#define O_INT  58427968ULL     // ints: CNT[8064], ROWPTR[8064], CSRSRC[72000]
__device__ float g_buf[58600000];

// ===========================================================================
// bf16 mma.sync GEMM, 2-stage cp.async pipeline + ldmatrix, 2 CTAs/SM.
// C[M, Ntot] = A[M,K] @ BT[Ntot,K]^T, fp32 accum, OUTPUT IN BF16.
// Cols [0,HC) -> XL, [HC,2HC) -> XR. K%64==0, Ntot%128==0, HC%128==0.
#define BM 128
#define BN 128
#define BK 64
#define AST 72                       // bf16 row stride (64 data + 8 pad) = 144B
#define TILE_BH (BM * AST)
#define TILE_B  (TILE_BH * 2)        // 18432 B
#define NSTAGE 2
#define SMEM_GEMM (NSTAGE * 2 * TILE_B)   // 73728 B -> 2 CTAs/SM

#define LDSM_X4(r0, r1, r2, r3, addr) \
    asm volatile("ldmatrix.sync.aligned.m8n8.x4.shared.b16 {%0,%1,%2,%3}, [%4];" \
        : "=r"(r0), "=r"(r1), "=r"(r2), "=r"(r3) : "r"(addr))

#define CP_ASYNC16(dst, src, sz) \
    asm volatile("cp.async.cg.shared.global [%0], [%1], 16, %2;" \
        :: "r"(dst), "l"(src), "r"(sz))

__global__ __launch_bounds__(256, 2) void gemm_bf16_k(
    const __nv_bfloat16* __restrict__ A, int lda,
    const __nv_bfloat16* __restrict__ BT, int ldb,
    __nv_bfloat16* __restrict__ XL, __nv_bfloat16* __restrict__ XR,
    int M, int K, int HC)
{
    extern __shared__ __nv_bfloat16 smem[];
    const uint32_t smb = (uint32_t)__cvta_generic_to_shared(smem);
    int tid = threadIdx.x;
    int lane = tid & 31, wid = tid >> 5;
    int wm = wid & 3, wn = wid >> 2;      // warp grid 4(m) x 2(n), tile 32x64
    int m0 = blockIdx.y * BM, n0 = blockIdx.x * BN;

    // ldmatrix per-lane addressing
    int j = lane >> 3, sub = lane & 7;
    int mfrag = ((j & 1) << 3) + sub;     // A: m_block = j&1, k_block = j>>1
    int kfragA = (j >> 1) << 3;
    int nfrag = ((j >> 1) << 3) + sub;    // B: n_block = j>>1, k_block = j&1
    int kfragB = (j & 1) << 3;

    // cp.async per-thread addressing
    int row_ld = tid >> 3;                // 0..31
    int ch_ld = tid & 7;                  // 16B chunk 0..7

    float acc[2][8][4];
#pragma unroll
    for (int i = 0; i < 2; i++)
#pragma unroll
        for (int q = 0; q < 8; q++)
#pragma unroll
            for (int v = 0; v < 4; v++) acc[i][q][v] = 0.f;

    int ntiles = K / BK;

    auto load_stage = [&](int s, int k0) {
        uint32_t abase = smb + s * 2 * TILE_B;
        uint32_t bbase = abase + TILE_B;
#pragma unroll
        for (int i = 0; i < 4; i++) {
            int r = row_ld + i * 32;
            int m = m0 + r;
            const __nv_bfloat16* srcA =
                A + (size_t)(m < M ? m : 0) * lda + k0 + ch_ld * 8;
            uint32_t dstA = abase + (uint32_t)(r * AST + ch_ld * 8) * 2;
            CP_ASYNC16(dstA, srcA, (m < M) ? 16 : 0);
            const __nv_bfloat16* srcB = BT + (size_t)(n0 + r) * ldb + k0 + ch_ld * 8;
            uint32_t dstB = bbase + (uint32_t)(r * AST + ch_ld * 8) * 2;
            CP_ASYNC16(dstB, srcB, 16);
        }
        asm volatile("cp.async.commit_group;");
    };

    load_stage(0, 0);

    for (int t = 0; t < ntiles; t++) {
        if (t + 1 < ntiles) {
            load_stage((t + 1) & 1, (t + 1) * BK);
            asm volatile("cp.async.wait_group 1;");
        } else {
            asm volatile("cp.async.wait_group 0;");
        }
        __syncthreads();

        int s = t & 1;
        uint32_t abase = smb + s * 2 * TILE_B;
        uint32_t bbase = abase + TILE_B;
#pragma unroll
        for (int ks = 0; ks < 4; ks++) {
            uint32_t af[2][4];
#pragma unroll
            for (int mt = 0; mt < 2; mt++) {
                uint32_t addr = abase +
                    (uint32_t)((wm * 32 + mt * 16 + mfrag) * AST + ks * 16 + kfragA) * 2;
                LDSM_X4(af[mt][0], af[mt][1], af[mt][2], af[mt][3], addr);
            }
            uint32_t bf[8][2];
#pragma unroll
            for (int np = 0; np < 4; np++) {
                uint32_t r0, r1, r2, r3;
                uint32_t addr = bbase +
                    (uint32_t)((wn * 64 + np * 16 + nfrag) * AST + ks * 16 + kfragB) * 2;
                LDSM_X4(r0, r1, r2, r3, addr);
                bf[2 * np][0] = r0;     bf[2 * np][1] = r1;
                bf[2 * np + 1][0] = r2; bf[2 * np + 1][1] = r3;
            }
#pragma unroll
            for (int mt = 0; mt < 2; mt++)
#pragma unroll
                for (int nt = 0; nt < 8; nt++) {
                    asm volatile(
                        "mma.sync.aligned.m16n8k16.row.col.f32.bf16.bf16.f32 "
                        "{%0,%1,%2,%3}, {%4,%5,%6,%7}, {%8,%9}, {%0,%1,%2,%3};"
                        : "+f"(acc[mt][nt][0]), "+f"(acc[mt][nt][1]),
                          "+f"(acc[mt][nt][2]), "+f"(acc[mt][nt][3])
                        : "r"(af[mt][0]), "r"(af[mt][1]), "r"(af[mt][2]), "r"(af[mt][3]),
                          "r"(bf[nt][0]), "r"(bf[nt][1]));
                }
        }
        __syncthreads();
    }

    // epilogue: convert fp32 acc -> bf16 pairs (HC % 128 == 0)
    int g = lane >> 2, tq = lane & 3;
    __nv_bfloat16* Cout;
    int cbase;
    if (n0 < HC) { Cout = XL; cbase = n0; }
    else         { Cout = XR; cbase = n0 - HC; }
#pragma unroll
    for (int mt = 0; mt < 2; mt++) {
        int m = m0 + wm * 32 + mt * 16 + g;
#pragma unroll
        for (int nt = 0; nt < 8; nt++) {
            int c = cbase + wn * 64 + nt * 8 + 2 * tq;
            if (m < M) {
                __nv_bfloat162 v;
                v.x = __float2bfloat16(acc[mt][nt][0]);
                v.y = __float2bfloat16(acc[mt][nt][1]);
                *(__nv_bfloat162*)(Cout + (size_t)m * HC + c) = v;
            }
            if (m + 8 < M) {
                __nv_bfloat162 v;
                v.x = __float2bfloat16(acc[mt][nt][2]);
                v.y = __float2bfloat16(acc[mt][nt][3]);
                *(__nv_bfloat162*)(Cout + (size_t)(m + 8) * HC + c) = v;
            }
        }
    }
}

// ===========================================================================
// Fused dual weight transpose (fp32 -> bf16): z selects Wl/Wr.
__global__ void transpose2_bf_k(const float* __restrict__ W0, const float* __restrict__ W1,
                                __nv_bfloat16* __restrict__ WT, size_t halfoff,
                                int K, int Nc, int ldbt) {
    __shared__ float t[32][33];
    const float* W = blockIdx.z ? W1 : W0;
    __nv_bfloat16* dst = WT + (size_t)blockIdx.z * halfoff;
    int n0 = blockIdx.x * 32, k0 = blockIdx.y * 32;
#pragma unroll
    for (int i = 0; i < 32; i += 8) {
        int k = k0 + threadIdx.y + i, n = n0 + threadIdx.x;
        if (k < K && n < Nc) t[threadIdx.y + i][threadIdx.x] = W[(size_t)k * Nc + n];
    }
    __syncthreads();
#pragma unroll
    for (int i = 0; i < 32; i += 8) {
        int n = n0 + threadIdx.y + i, k = k0 + threadIdx.x;
        if (k < K && n < Nc) dst[(size_t)n * ldbt + k] = __float2bfloat16(t[threadIdx.x][threadIdx.y + i]);
    }
}

// ===========================================================================
// CSR build (edges + self loops, grouped by dst). CNT zero at entry;
// scatter drains it back to zero (self-cleaning, replay-safe).
__device__ __forceinline__ void edge_ep(const int* __restrict__ ei, int E, int e, int& s, int& d) {
    if (e < E) { s = ei[e]; d = ei[E + e]; }
    else       { s = e - E; d = e - E; }
}
__global__ void hist_k(const int* __restrict__ ei, int E, int Etot, int* __restrict__ cnt) {
    int i = blockIdx.x * blockDim.x + threadIdx.x;
    if (i >= Etot) return;
    int s, d; edge_ep(ei, E, i, s, d);
    atomicAdd(&cnt[d], 1);
}
__global__ void scan8000_k(const int* __restrict__ cnt, int* __restrict__ rowptr, int n) {
    __shared__ int sh[1024];
    int tid = threadIdx.x;
    int vals[8]; int s = 0;
#pragma unroll
    for (int q = 0; q < 8; q++) {
        int i = tid * 8 + q;
        vals[q] = (i < n) ? cnt[i] : 0;
        s += vals[q];
    }
    sh[tid] = s; __syncthreads();
    for (int off = 1; off < 1024; off <<= 1) {
        int v = (tid >= off) ? sh[tid - off] : 0;
        __syncthreads();
        sh[tid] += v;
        __syncthreads();
    }
    int run = sh[tid] - s;
#pragma unroll
    for (int q = 0; q < 8; q++) {
        int i = tid * 8 + q;
        if (i < n) rowptr[i] = run;
        run += vals[q];
    }
    if (tid == 1023) rowptr[n] = run;
}
__global__ void scatter_k(const int* __restrict__ ei, int E, int Etot,
                          const int* __restrict__ rowptr, int* __restrict__ cnt,
                          int* __restrict__ csr_src) {
    int i = blockIdx.x * blockDim.x + threadIdx.x;
    if (i >= Etot) return;
    int s, d; edge_ep(ei, E, i, s, d);
    int old = atomicAdd(&cnt[d], -1);        // drains cnt back to zero
    csr_src[rowptr[d] + old - 1] = s;
}

// ===========================================================================
// BatchNorm stats accumulate (SUM/SQ zero at entry; node_warp of this layer
// re-zeroes them after bn_apply has consumed them).
__global__ void colstats_k(const float* __restrict__ H, int ldi, int Nn, int F, int rows_per,
                           float* __restrict__ sum, float* __restrict__ sq) {
    int col = blockIdx.x * blockDim.x + threadIdx.x;
    if (col >= F) return;
    int r0 = blockIdx.y * rows_per;
    int r1 = min(r0 + rows_per, Nn);
    float s = 0.f, q = 0.f;
    for (int r = r0; r < r1; r++) {
        float v = H[(size_t)r * ldi + col];
        s += v; q += v * v;
    }
    atomicAdd(&sum[col], s);
    atomicAdd(&sq[col], q);
}
// BN apply with inline mean/rstd from SUM/SQ, writing packed bf16.
__global__ void bn_apply_bf_k(const float* __restrict__ X, int ldi,
                              __nv_bfloat16* __restrict__ O, int ldo,
                              long long total, int F, int Nn,
                              const float* __restrict__ sum, const float* __restrict__ sq,
                              const float* __restrict__ g, const float* __restrict__ b, int relu) {
    long long i = (long long)blockIdx.x * blockDim.x + threadIdx.x;
    long long st = (long long)gridDim.x * blockDim.x;
    float invN = 1.f / (float)Nn;
    for (; i < total; i += st) {
        int r = (int)(i / F), c = (int)(i % F);
        float m = sum[c] * invN;
        float var = sq[c] * invN - m * m;
        var = var > 0.f ? var : 0.f;
        float rs = rsqrtf(var + 1e-5f);
        float v = (X[(size_t)r * ldi + c] - m) * rs * g[c] + b[c];
        if (relu) v = fmaxf(v, 0.f);
        O[(size_t)r * ldo + c] = __float2bfloat16(v);
    }
}

// ===========================================================================
// bf16 quad load -> float4
__device__ __forceinline__ float4 ld_bf4(const __nv_bfloat16* p) {
    __nv_bfloat162 v01 = *(const __nv_bfloat162*)p;
    __nv_bfloat162 v23 = *(const __nv_bfloat162*)(p + 2);
    return make_float4(__bfloat162float(v01.x), __bfloat162float(v01.y),
                       __bfloat162float(v23.x), __bfloat162float(v23.y));
}

// Warp-per-(node,head) fused GATv2 edge stage over bf16 xl/xr: online segment
// softmax + weighted aggregation + mean + bias (+relu), f32 math, no syncs.
// Block 0 additionally zeroes this layer's SUM/SQ (runs after bn_apply).
__global__ __launch_bounds__(256) void node_warp_k(
    const int* __restrict__ rowptr, const int* __restrict__ csr_src,
    const __nv_bfloat16* __restrict__ xl, const __nv_bfloat16* __restrict__ xr,
    const float* __restrict__ att, const float* __restrict__ bias,
    float* __restrict__ out, int H, int relu, int NH,
    float* __restrict__ cln, int cln_n)
{
    if (blockIdx.x == 0) {
        for (int i = threadIdx.x; i < cln_n; i += blockDim.x) cln[i] = 0.f;
    }
    int w = (blockIdx.x * blockDim.x + threadIdx.x) >> 5;
    int lane = threadIdx.x & 31;
    if (w >= NH) return;
    int n = w / H, h = w - n * H;
    size_t base = (size_t)w * 512;          // == (n*H + h)*512

    float4 xr4[4], at4[4];
#pragma unroll
    for (int g = 0; g < 4; g++) {
        xr4[g] = ld_bf4(xr + base + lane * 4 + g * 128);
        at4[g] = *(const float4*)(att + (size_t)h * 512 + lane * 4 + g * 128);
    }

    int r0 = rowptr[n], r1 = rowptr[n + 1];
    float m = -3.4e38f, d = 0.f;
    float4 acc4[4];
#pragma unroll
    for (int g = 0; g < 4; g++) acc4[g] = make_float4(0.f, 0.f, 0.f, 0.f);

    float4 l4[4];
    {
        size_t sb = ((size_t)csr_src[r0] * H + h) * 512;
#pragma unroll
        for (int g = 0; g < 4; g++) l4[g] = ld_bf4(xl + sb + lane * 4 + g * 128);
    }

    for (int i = r0; i < r1; i++) {
        float4 nl4[4];
        if (i + 1 < r1) {
            size_t sb = ((size_t)csr_src[i + 1] * H + h) * 512;
#pragma unroll
            for (int g = 0; g < 4; g++) nl4[g] = ld_bf4(xl + sb + lane * 4 + g * 128);
        }
        float part = 0.f;
#pragma unroll
        for (int g = 0; g < 4; g++) {
            float z;
            z = l4[g].x + xr4[g].x; z = z > 0.f ? z : 0.2f * z; part += at4[g].x * z;
            z = l4[g].y + xr4[g].y; z = z > 0.f ? z : 0.2f * z; part += at4[g].y * z;
            z = l4[g].z + xr4[g].z; z = z > 0.f ? z : 0.2f * z; part += at4[g].z * z;
            z = l4[g].w + xr4[g].w; z = z > 0.f ? z : 0.2f * z; part += at4[g].w * z;
        }
#pragma unroll
        for (int o = 16; o; o >>= 1) part += __shfl_xor_sync(0xffffffffu, part, o);
        float mn = fmaxf(m, part);
        float f = __expf(m - mn), e = __expf(part - mn);
        d = d * f + e;
#pragma unroll
        for (int g = 0; g < 4; g++) {
            acc4[g].x = acc4[g].x * f + e * l4[g].x;
            acc4[g].y = acc4[g].y * f + e * l4[g].y;
            acc4[g].z = acc4[g].z * f + e * l4[g].z;
            acc4[g].w = acc4[g].w * f + e * l4[g].w;
        }
        m = mn;
        if (i + 1 < r1) {
#pragma unroll
            for (int g = 0; g < 4; g++) l4[g] = nl4[g];
        }
    }
    float inv = 1.f / (d * (float)(r1 - r0));
#pragma unroll
    for (int g = 0; g < 4; g++) {
        float4 bv = *(const float4*)(bias + (size_t)h * 512 + lane * 4 + g * 128);
        float4 o4;
        o4.x = acc4[g].x * inv + bv.x;
        o4.y = acc4[g].y * inv + bv.y;
        o4.z = acc4[g].z * inv + bv.z;
        o4.w = acc4[g].w * inv + bv.w;
        if (relu) {
            o4.x = fmaxf(o4.x, 0.f); o4.y = fmaxf(o4.y, 0.f);
            o4.z = fmaxf(o4.z, 0.f); o4.w = fmaxf(o4.w, 0.f);
        }
        *(float4*)(out + base + lane * 4 + g * 128) = o4;
    }
}

// ===========================================================================
// Fused head + gather: evaluate sigmoid head only at train indices.
__global__ void headgather_k(const float* __restrict__ h, const float* __restrict__ Wh,
                             const float* __restrict__ bh, const float* __restrict__ y,
                             const int* __restrict__ idx, float* __restrict__ out, int NT) {
    int warp = (blockIdx.x * blockDim.x + threadIdx.x) >> 5;
    int lane = threadIdx.x & 31;
    if (warp >= NT) return;
    int n = idx[warp];
    const float* p = h + (size_t)n * 512;
    float acc = 0.f;
#pragma unroll
    for (int c = lane; c < 512; c += 32) acc += p[c] * Wh[c];
#pragma unroll
    for (int o = 16; o; o >>= 1) acc += __shfl_xor_sync(0xffffffffu, acc, o);
    if (lane == 0) {
        float x = acc + bh[0];
        out[warp] = 1.f / (1.f + __expf(-x));
        out[NT + warp] = y[n];
    }
}

// ===========================================================================
extern "C" void kernel_launch(void* const* d_in, const int* in_sizes, int n_in,
                              void* d_out, int out_size) {
    const float* x     = (const float*)d_in[0];
    const int*   ei    = (const int*)d_in[1];
    const float* y     = (const float*)d_in[2];
    const int*   tidx  = (const int*)d_in[3];
    const float* bn0_g = (const float*)d_in[4];
    const float* bn0_b = (const float*)d_in[5];
    const float* W1l = (const float*)d_in[6],  *W1r = (const float*)d_in[7];
    const float* a1  = (const float*)d_in[8],  *b1  = (const float*)d_in[9];
    const float* bn1_g = (const float*)d_in[10], *bn1_b = (const float*)d_in[11];
    const float* W2l = (const float*)d_in[12], *W2r = (const float*)d_in[13];
    const float* a2  = (const float*)d_in[14], *b2  = (const float*)d_in[15];
    const float* bn2_g = (const float*)d_in[16], *bn2_b = (const float*)d_in[17];
    const float* W3l = (const float*)d_in[18], *W3r = (const float*)d_in[19];
    const float* a3  = (const float*)d_in[20], *b3  = (const float*)d_in[21];
    const float* bn3_g = (const float*)d_in[22], *bn3_b = (const float*)d_in[23];
    const float* W4l = (const float*)d_in[24], *W4r = (const float*)d_in[25];
    const float* a4  = (const float*)d_in[26], *b4  = (const float*)d_in[27];
    const float* Wh  = (const float*)d_in[28], *bh  = (const float*)d_in[29];

    const int Nn   = in_sizes[2];        // 8000
    const int FINv = in_sizes[0] / Nn;   // 3201
    const int E    = in_sizes[1] / 2;    // 64000
    const int Etot = E + Nn;
    const int NT   = in_sizes[3];

    float* buf = nullptr;
    cudaGetSymbolAddress((void**)&buf, g_buf);
    __nv_bfloat16* A1  = (__nv_bfloat16*)(buf + O_A1);
    __nv_bfloat16* A2  = (__nv_bfloat16*)(buf + O_A2);
    __nv_bfloat16* XL  = (__nv_bfloat16*)(buf + O_XL);
    __nv_bfloat16* XR  = (__nv_bfloat16*)(buf + O_XR);
    float* H1 = buf + O_H1;
    float* H2 = buf + O_H2;
    float* H3 = buf + O_H3;
    float* H4 = buf + O_H4;
    __nv_bfloat16* BT1 = (__nv_bfloat16*)(buf + O_BT1);
    __nv_bfloat16* BT2 = (__nv_bfloat16*)(buf + O_BT2);
    __nv_bfloat16* BT3 = (__nv_bfloat16*)(buf + O_BT3);
    __nv_bfloat16* BT4 = (__nv_bfloat16*)(buf + O_BT4);
    float* ST1 = buf + O_STAT;              // 2*3264
    float* ST2 = ST1 + 2 * 3264;            // 2*1024
    float* ST3 = ST2 + 2 * 1024;            // 2*512
    float* ST4 = ST3 + 2 * 512;             // 2*512
    int* CNT    = (int*)(buf + O_INT);
    int* ROWPTR = CNT + 8064;
    int* CSRSRC = ROWPTR + 8064;

    const int rows_per = (Nn + 31) / 32;
    const int GY = (Nn + BM - 1) / BM;

    cudaFuncSetAttribute(gemm_bf16_k, cudaFuncAttributeMaxDynamicSharedMemorySize, SMEM_GEMM);

    // ---- side stream + events (created once; capture-legal fork/join)
    static cudaStream_t s1 = nullptr;
    static cudaEvent_t ev_fork, ev_t1, ev_csr, ev_t2, ev_t3, ev_t4;
    if (s1 == nullptr) {
        cudaStreamCreateWithFlags(&s1, cudaStreamNonBlocking);
        cudaEventCreateWithFlags(&ev_fork, cudaEventDisableTiming);
        cudaEventCreateWithFlags(&ev_t1, cudaEventDisableTiming);
        cudaEventCreateWithFlags(&ev_csr, cudaEventDisableTiming);
        cudaEventCreateWithFlags(&ev_t2, cudaEventDisableTiming);
        cudaEventCreateWithFlags(&ev_t3, cudaEventDisableTiming);
        cudaEventCreateWithFlags(&ev_t4, cudaEventDisableTiming);
    }

    auto run_bn = [&](const float* in, int ldi, __nv_bfloat16* out, int ldo, int F,
                      float* ST, const float* g, const float* b, int relu) {
        dim3 grid((F + 255) / 256, 32);
        colstats_k<<<grid, 256>>>(in, ldi, Nn, F, rows_per, ST, ST + F);
        bn_apply_bf_k<<<2048, 256>>>(in, ldi, out, ldo, (long long)Nn * F, F, Nn,
                                     ST, ST + F, g, b, relu);
    };
    auto run_tr2_s1 = [&](const float* Wl, const float* Wr, __nv_bfloat16* BT,
                          int K, int Nc, int ldbt) {
        dim3 tg(Nc / 32, (K + 31) / 32, 2);
        transpose2_bf_k<<<tg, dim3(32, 8), 0, s1>>>(Wl, Wr, BT, (size_t)Nc * ldbt, K, Nc, ldbt);
    };

    // ---- fork side stream: all input-only prep work runs concurrently
    cudaEventRecord(ev_fork, 0);
    cudaStreamWaitEvent(s1, ev_fork, 0);
    run_tr2_s1(W1l, W1r, BT1, FINv, 1024, LDA0);
    cudaEventRecord(ev_t1, s1);
    hist_k<<<(Etot + 255) / 256, 256, 0, s1>>>(ei, E, Etot, CNT);
    scan8000_k<<<1, 1024, 0, s1>>>(CNT, ROWPTR, Nn);
    scatter_k<<<(Etot + 255) / 256, 256, 0, s1>>>(ei, E, Etot, ROWPTR, CNT, CSRSRC);
    cudaEventRecord(ev_csr, s1);
    run_tr2_s1(W2l, W2r, BT2, 1024, 512, 1024);
    cudaEventRecord(ev_t2, s1);
    run_tr2_s1(W3l, W3r, BT3, 512, 512, 512);
    cudaEventRecord(ev_t3, s1);
    run_tr2_s1(W4l, W4r, BT4, 512, 512, 512);
    cudaEventRecord(ev_t4, s1);

    // ---- main stream: layer 1
    run_bn(x, FINv, A1, LDA0, FINv, ST1, bn0_g, bn0_b, 0);
    cudaStreamWaitEvent(0, ev_t1, 0);
    gemm_bf16_k<<<dim3(2048 / BN, GY), 256, SMEM_GEMM>>>(A1, LDA0, BT1, LDA0, XL, XR, Nn, LDA0, 1024);
    cudaStreamWaitEvent(0, ev_csr, 0);
    node_warp_k<<<(Nn * 2 * 32 + 255) / 256, 256>>>(ROWPTR, CSRSRC, XL, XR, a1, b1, H1, 2, 0,
                                                    Nn * 2, ST1, 2 * 3264);

    // ---- layer 2
    run_bn(H1, 1024, A2, 1024, 1024, ST2, bn1_g, bn1_b, 1);
    cudaStreamWaitEvent(0, ev_t2, 0);
    gemm_bf16_k<<<dim3(1024 / BN, GY), 256, SMEM_GEMM>>>(A2, 1024, BT2, 1024, XL, XR, Nn, 1024, 512);
    node_warp_k<<<(Nn * 32 + 255) / 256, 256>>>(ROWPTR, CSRSRC, XL, XR, a2, b2, H2, 1, 0,
                                                Nn, ST2, 2 * 1024);

    // ---- layer 3
    run_bn(H2, 512, A2, 512, 512, ST3, bn2_g, bn2_b, 1);
    cudaStreamWaitEvent(0, ev_t3, 0);
    gemm_bf16_k<<<dim3(1024 / BN, GY), 256, SMEM_GEMM>>>(A2, 512, BT3, 512, XL, XR, Nn, 512, 512);
    node_warp_k<<<(Nn * 32 + 255) / 256, 256>>>(ROWPTR, CSRSRC, XL, XR, a3, b3, H3, 1, 0,
                                                Nn, ST3, 2 * 512);

    // ---- layer 4 (relu fused into edge stage)
    run_bn(H3, 512, A2, 512, 512, ST4, bn3_g, bn3_b, 1);
    cudaStreamWaitEvent(0, ev_t4, 0);
    gemm_bf16_k<<<dim3(1024 / BN, GY), 256, SMEM_GEMM>>>(A2, 512, BT4, 512, XL, XR, Nn, 512, 512);
    node_warp_k<<<(Nn * 32 + 255) / 256, 256>>>(ROWPTR, CSRSRC, XL, XR, a4, b4, H4, 1, 1,
                                                Nn, ST4, 2 * 512);

    // ---- fused head + gather (train indices only)
    headgather_k<<<(NT * 32 + 255) / 256, 256>>>(H4, Wh, bh, y, tidx, (float*)d_out, NT);
}

// round 14
// speedup vs baseline: 1.0082x; 1.0082x over previous
#include <cuda_runtime.h>
#include <cuda_bf16.h>
#include <cstdint>

// ===========================================================================
#define LDA0 3264            // 3201 padded to /64 (bf16 elems)

// float-offset layout (g_buf zero-initialized at load; pad regions never
// written -> statically zero across all calls)
#define O_A1   0ULL            // bf16 [8000*3264]
#define O_A2   13056000ULL     // bf16 [8000*1024] (also layers 3/4 with ld 512)
#define O_XL   17152000ULL     // bf16 8000*1024 (half of f32-sized slot used)
#define O_XR   25344000ULL     // bf16 8000*1024
#define O_H1   33536000ULL     // f32 8000*1024
#define O_H2   41728000ULL     // f32 8000*512
#define O_H3   45824000ULL     // f32 8000*512
#define O_H4   49920000ULL     // f32 8000*512
#define O_BT1  54016000ULL     // bf16 2048*3264
#define O_BT2  57358336ULL     // bf16 1024*1024
#define O_BT3  57882624ULL     // bf16 1024*512
#define O_BT4  58144768ULL     // bf16 1024*512
#define O_STAT 58406912ULL     // per-layer SUM/SQ: L1 2*3264, L2 2*1024, L3/L4 2*512
#define O_INT  58427968ULL     // ints: CNT[8064], ROWPTR[8064], CSRSRC[72000]
__device__ float g_buf[58600000];

// ===========================================================================
// bf16 mma.sync GEMM, 2-stage cp.async pipeline + ldmatrix, 2 CTAs/SM.
// C[M, Ntot] = A[M,K] @ BT[Ntot,K]^T, fp32 accum, output bf16.
// Cols [0,HC) -> XL, [HC,2HC) -> XR. K%64==0, Ntot%128==0, HC%128==0.
#define BM 128
#define BN 128
#define BK 64
#define AST 72                       // bf16 row stride (64 data + 8 pad) = 144B
#define TILE_BH (BM * AST)
#define TILE_B  (TILE_BH * 2)        // 18432 B
#define NSTAGE 2
#define SMEM_GEMM (NSTAGE * 2 * TILE_B)   // 73728 B -> 2 CTAs/SM

#define LDSM_X4(r0, r1, r2, r3, addr) \
    asm volatile("ldmatrix.sync.aligned.m8n8.x4.shared.b16 {%0,%1,%2,%3}, [%4];" \
        : "=r"(r0), "=r"(r1), "=r"(r2), "=r"(r3) : "r"(addr))

#define CP_ASYNC16(dst, src, sz) \
    asm volatile("cp.async.cg.shared.global [%0], [%1], 16, %2;" \
        :: "r"(dst), "l"(src), "r"(sz))

__global__ __launch_bounds__(256, 2) void gemm_bf16_k(
    const __nv_bfloat16* __restrict__ A, int lda,
    const __nv_bfloat16* __restrict__ BT, int ldb,
    __nv_bfloat16* __restrict__ XL, __nv_bfloat16* __restrict__ XR,
    int M, int K, int HC)
{
    extern __shared__ __nv_bfloat16 smem[];
    const uint32_t smb = (uint32_t)__cvta_generic_to_shared(smem);
    int tid = threadIdx.x;
    int lane = tid & 31, wid = tid >> 5;
    int wm = wid & 3, wn = wid >> 2;      // warp grid 4(m) x 2(n), tile 32x64
    int m0 = blockIdx.y * BM, n0 = blockIdx.x * BN;

    // ldmatrix per-lane addressing
    int j = lane >> 3, sub = lane & 7;
    int mfrag = ((j & 1) << 3) + sub;     // A: m_block = j&1, k_block = j>>1
    int kfragA = (j >> 1) << 3;
    int nfrag = ((j >> 1) << 3) + sub;    // B: n_block = j>>1, k_block = j&1
    int kfragB = (j & 1) << 3;

    // cp.async per-thread addressing
    int row_ld = tid >> 3;                // 0..31
    int ch_ld = tid & 7;                  // 16B chunk 0..7

    float acc[2][8][4];
#pragma unroll
    for (int i = 0; i < 2; i++)
#pragma unroll
        for (int q = 0; q < 8; q++)
#pragma unroll
            for (int v = 0; v < 4; v++) acc[i][q][v] = 0.f;

    int ntiles = K / BK;

    auto load_stage = [&](int s, int k0) {
        uint32_t abase = smb + s * 2 * TILE_B;
        uint32_t bbase = abase + TILE_B;
#pragma unroll
        for (int i = 0; i < 4; i++) {
            int r = row_ld + i * 32;
            int m = m0 + r;
            const __nv_bfloat16* srcA =
                A + (size_t)(m < M ? m : 0) * lda + k0 + ch_ld * 8;
            uint32_t dstA = abase + (uint32_t)(r * AST + ch_ld * 8) * 2;
            CP_ASYNC16(dstA, srcA, (m < M) ? 16 : 0);
            const __nv_bfloat16* srcB = BT + (size_t)(n0 + r) * ldb + k0 + ch_ld * 8;
            uint32_t dstB = bbase + (uint32_t)(r * AST + ch_ld * 8) * 2;
            CP_ASYNC16(dstB, srcB, 16);
        }
        asm volatile("cp.async.commit_group;");
    };

    load_stage(0, 0);

    for (int t = 0; t < ntiles; t++) {
        if (t + 1 < ntiles) {
            load_stage((t + 1) & 1, (t + 1) * BK);
            asm volatile("cp.async.wait_group 1;");
        } else {
            asm volatile("cp.async.wait_group 0;");
        }
        __syncthreads();

        int s = t & 1;
        uint32_t abase = smb + s * 2 * TILE_B;
        uint32_t bbase = abase + TILE_B;
#pragma unroll
        for (int ks = 0; ks < 4; ks++) {
            uint32_t af[2][4];
#pragma unroll
            for (int mt = 0; mt < 2; mt++) {
                uint32_t addr = abase +
                    (uint32_t)((wm * 32 + mt * 16 + mfrag) * AST + ks * 16 + kfragA) * 2;
                LDSM_X4(af[mt][0], af[mt][1], af[mt][2], af[mt][3], addr);
            }
            uint32_t bf[8][2];
#pragma unroll
            for (int np = 0; np < 4; np++) {
                uint32_t r0, r1, r2, r3;
                uint32_t addr = bbase +
                    (uint32_t)((wn * 64 + np * 16 + nfrag) * AST + ks * 16 + kfragB) * 2;
                LDSM_X4(r0, r1, r2, r3, addr);
                bf[2 * np][0] = r0;     bf[2 * np][1] = r1;
                bf[2 * np + 1][0] = r2; bf[2 * np + 1][1] = r3;
            }
#pragma unroll
            for (int mt = 0; mt < 2; mt++)
#pragma unroll
                for (int nt = 0; nt < 8; nt++) {
                    asm volatile(
                        "mma.sync.aligned.m16n8k16.row.col.f32.bf16.bf16.f32 "
                        "{%0,%1,%2,%3}, {%4,%5,%6,%7}, {%8,%9}, {%0,%1,%2,%3};"
                        : "+f"(acc[mt][nt][0]), "+f"(acc[mt][nt][1]),
                          "+f"(acc[mt][nt][2]), "+f"(acc[mt][nt][3])
                        : "r"(af[mt][0]), "r"(af[mt][1]), "r"(af[mt][2]), "r"(af[mt][3]),
                          "r"(bf[nt][0]), "r"(bf[nt][1]));
                }
        }
        __syncthreads();
    }

    // epilogue: fp32 acc -> bf16 pairs (HC % 128 == 0)
    int g = lane >> 2, tq = lane & 3;
    __nv_bfloat16* Cout;
    int cbase;
    if (n0 < HC) { Cout = XL; cbase = n0; }
    else         { Cout = XR; cbase = n0 - HC; }
#pragma unroll
    for (int mt = 0; mt < 2; mt++) {
        int m = m0 + wm * 32 + mt * 16 + g;
#pragma unroll
        for (int nt = 0; nt < 8; nt++) {
            int c = cbase + wn * 64 + nt * 8 + 2 * tq;
            if (m < M) {
                __nv_bfloat162 v;
                v.x = __float2bfloat16(acc[mt][nt][0]);
                v.y = __float2bfloat16(acc[mt][nt][1]);
                *(__nv_bfloat162*)(Cout + (size_t)m * HC + c) = v;
            }
            if (m + 8 < M) {
                __nv_bfloat162 v;
                v.x = __float2bfloat16(acc[mt][nt][2]);
                v.y = __float2bfloat16(acc[mt][nt][3]);
                *(__nv_bfloat162*)(Cout + (size_t)(m + 8) * HC + c) = v;
            }
        }
    }
}

// ===========================================================================
// Fused dual weight transpose (fp32 -> bf16): z selects Wl/Wr.
__global__ void transpose2_bf_k(const float* __restrict__ W0, const float* __restrict__ W1,
                                __nv_bfloat16* __restrict__ WT, size_t halfoff,
                                int K, int Nc, int ldbt) {
    __shared__ float t[32][33];
    const float* W = blockIdx.z ? W1 : W0;
    __nv_bfloat16* dst = WT + (size_t)blockIdx.z * halfoff;
    int n0 = blockIdx.x * 32, k0 = blockIdx.y * 32;
#pragma unroll
    for (int i = 0; i < 32; i += 8) {
        int k = k0 + threadIdx.y + i, n = n0 + threadIdx.x;
        if (k < K && n < Nc) t[threadIdx.y + i][threadIdx.x] = W[(size_t)k * Nc + n];
    }
    __syncthreads();
#pragma unroll
    for (int i = 0; i < 32; i += 8) {
        int n = n0 + threadIdx.y + i, k = k0 + threadIdx.x;
        if (k < K && n < Nc) dst[(size_t)n * ldbt + k] = __float2bfloat16(t[threadIdx.x][threadIdx.y + i]);
    }
}

// ===========================================================================
// CSR build (edges + self loops, grouped by dst). CNT zero at entry;
// scatter drains it back to zero (self-cleaning, replay-safe).
__device__ __forceinline__ void edge_ep(const int* __restrict__ ei, int E, int e, int& s, int& d) {
    if (e < E) { s = ei[e]; d = ei[E + e]; }
    else       { s = e - E; d = e - E; }
}
__global__ void hist_k(const int* __restrict__ ei, int E, int Etot, int* __restrict__ cnt) {
    int i = blockIdx.x * blockDim.x + threadIdx.x;
    if (i >= Etot) return;
    int s, d; edge_ep(ei, E, i, s, d);
    atomicAdd(&cnt[d], 1);
}
__global__ void scan8000_k(const int* __restrict__ cnt, int* __restrict__ rowptr, int n) {
    __shared__ int sh[1024];
    int tid = threadIdx.x;
    int vals[8]; int s = 0;
#pragma unroll
    for (int q = 0; q < 8; q++) {
        int i = tid * 8 + q;
        vals[q] = (i < n) ? cnt[i] : 0;
        s += vals[q];
    }
    sh[tid] = s; __syncthreads();
    for (int off = 1; off < 1024; off <<= 1) {
        int v = (tid >= off) ? sh[tid - off] : 0;
        __syncthreads();
        sh[tid] += v;
        __syncthreads();
    }
    int run = sh[tid] - s;
#pragma unroll
    for (int q = 0; q < 8; q++) {
        int i = tid * 8 + q;
        if (i < n) rowptr[i] = run;
        run += vals[q];
    }
    if (tid == 1023) rowptr[n] = run;
}
__global__ void scatter_k(const int* __restrict__ ei, int E, int Etot,
                          const int* __restrict__ rowptr, int* __restrict__ cnt,
                          int* __restrict__ csr_src) {
    int i = blockIdx.x * blockDim.x + threadIdx.x;
    if (i >= Etot) return;
    int s, d; edge_ep(ei, E, i, s, d);
    int old = atomicAdd(&cnt[d], -1);        // drains cnt back to zero
    csr_src[rowptr[d] + old - 1] = s;
}

// ===========================================================================
// BatchNorm stats accumulate (SUM/SQ zero at entry; node_warp of this layer
// re-zeroes them after bn_apply has consumed them).
__global__ void colstats_k(const float* __restrict__ H, int ldi, int Nn, int F, int rows_per,
                           float* __restrict__ sum, float* __restrict__ sq) {
    int col = blockIdx.x * blockDim.x + threadIdx.x;
    if (col >= F) return;
    int r0 = blockIdx.y * rows_per;
    int r1 = min(r0 + rows_per, Nn);
    float s = 0.f, q = 0.f;
    for (int r = r0; r < r1; r++) {
        float v = H[(size_t)r * ldi + col];
        s += v; q += v * v;
    }
    atomicAdd(&sum[col], s);
    atomicAdd(&sq[col], q);
}
// BN apply with inline mean/rstd from SUM/SQ, writing packed bf16.
__global__ void bn_apply_bf_k(const float* __restrict__ X, int ldi,
                              __nv_bfloat16* __restrict__ O, int ldo,
                              long long total, int F, int Nn,
                              const float* __restrict__ sum, const float* __restrict__ sq,
                              const float* __restrict__ g, const float* __restrict__ b, int relu) {
    long long i = (long long)blockIdx.x * blockDim.x + threadIdx.x;
    long long st = (long long)gridDim.x * blockDim.x;
    float invN = 1.f / (float)Nn;
    for (; i < total; i += st) {
        int r = (int)(i / F), c = (int)(i % F);
        float m = sum[c] * invN;
        float var = sq[c] * invN - m * m;
        var = var > 0.f ? var : 0.f;
        float rs = rsqrtf(var + 1e-5f);
        float v = (X[(size_t)r * ldi + c] - m) * rs * g[c] + b[c];
        if (relu) v = fmaxf(v, 0.f);
        O[(size_t)r * ldo + c] = __float2bfloat16(v);
    }
}

// ===========================================================================
// 8 bf16 (one uint4) -> 8 f32
__device__ __forceinline__ void bf8_to_f32(uint4 v, float* o) {
    const __nv_bfloat162* p = reinterpret_cast<const __nv_bfloat162*>(&v);
#pragma unroll
    for (int i = 0; i < 4; i++) {
        float2 f = __bfloat1622float2(p[i]);
        o[2 * i] = f.x; o[2 * i + 1] = f.y;
    }
}

// Warp-per-(node,head) fused GATv2 edge stage over bf16 xl/xr (16B loads):
// online segment softmax + weighted aggregation + mean + bias (+relu),
// f32 math, no syncs. Block 0 zeroes this layer's SUM/SQ (after bn_apply).
// Lane owns cols lane*8 + g*256 + (0..7), g = 0..1.
__global__ __launch_bounds__(256) void node_warp_k(
    const int* __restrict__ rowptr, const int* __restrict__ csr_src,
    const __nv_bfloat16* __restrict__ xl, const __nv_bfloat16* __restrict__ xr,
    const float* __restrict__ att, const float* __restrict__ bias,
    float* __restrict__ out, int H, int relu, int NH,
    float* __restrict__ cln, int cln_n)
{
    if (blockIdx.x == 0) {
        for (int i = threadIdx.x; i < cln_n; i += blockDim.x) cln[i] = 0.f;
    }
    int w = (blockIdx.x * blockDim.x + threadIdx.x) >> 5;
    int lane = threadIdx.x & 31;
    if (w >= NH) return;
    int n = w / H, h = w - n * H;
    size_t base = (size_t)w * 512;          // == (n*H + h)*512

    float xr8[2][8], at8[2][8], acc8[2][8], l8[2][8];
#pragma unroll
    for (int g = 0; g < 2; g++) {
        int c0 = lane * 8 + g * 256;
        bf8_to_f32(*(const uint4*)(xr + base + c0), xr8[g]);
#pragma unroll
        for (int q = 0; q < 8; q += 4)
            *(float4*)&at8[g][q] = *(const float4*)(att + (size_t)h * 512 + c0 + q);
#pragma unroll
        for (int q = 0; q < 8; q++) acc8[g][q] = 0.f;
    }

    int r0 = rowptr[n], r1 = rowptr[n + 1];
    float m = -3.4e38f, d = 0.f;
    {
        size_t sb = ((size_t)csr_src[r0] * H + h) * 512;
#pragma unroll
        for (int g = 0; g < 2; g++)
            bf8_to_f32(*(const uint4*)(xl + sb + lane * 8 + g * 256), l8[g]);
    }

    for (int i = r0; i < r1; i++) {
        float nl8[2][8];
        if (i + 1 < r1) {
            size_t sb = ((size_t)csr_src[i + 1] * H + h) * 512;
#pragma unroll
            for (int g = 0; g < 2; g++)
                bf8_to_f32(*(const uint4*)(xl + sb + lane * 8 + g * 256), nl8[g]);
        }
        float part = 0.f;
#pragma unroll
        for (int g = 0; g < 2; g++)
#pragma unroll
            for (int q = 0; q < 8; q++) {
                float z = l8[g][q] + xr8[g][q];
                z = z > 0.f ? z : 0.2f * z;
                part += at8[g][q] * z;
            }
#pragma unroll
        for (int o = 16; o; o >>= 1) part += __shfl_xor_sync(0xffffffffu, part, o);
        float mn = fmaxf(m, part);
        float f = __expf(m - mn), e = __expf(part - mn);
        d = d * f + e;
#pragma unroll
        for (int g = 0; g < 2; g++)
#pragma unroll
            for (int q = 0; q < 8; q++)
                acc8[g][q] = acc8[g][q] * f + e * l8[g][q];
        m = mn;
        if (i + 1 < r1) {
#pragma unroll
            for (int g = 0; g < 2; g++)
#pragma unroll
                for (int q = 0; q < 8; q++) l8[g][q] = nl8[g][q];
        }
    }
    float inv = 1.f / (d * (float)(r1 - r0));
#pragma unroll
    for (int g = 0; g < 2; g++) {
        int c0 = lane * 8 + g * 256;
#pragma unroll
        for (int q = 0; q < 8; q += 4) {
            float4 bv = *(const float4*)(bias + (size_t)h * 512 + c0 + q);
            float4 o4;
            o4.x = acc8[g][q + 0] * inv + bv.x;
            o4.y = acc8[g][q + 1] * inv + bv.y;
            o4.z = acc8[g][q + 2] * inv + bv.z;
            o4.w = acc8[g][q + 3] * inv + bv.w;
            if (relu) {
                o4.x = fmaxf(o4.x, 0.f); o4.y = fmaxf(o4.y, 0.f);
                o4.z = fmaxf(o4.z, 0.f); o4.w = fmaxf(o4.w, 0.f);
            }
            *(float4*)(out + base + c0 + q) = o4;
        }
    }
}

// ===========================================================================
// Fused head + gather: evaluate sigmoid head only at train indices.
__global__ void headgather_k(const float* __restrict__ h, const float* __restrict__ Wh,
                             const float* __restrict__ bh, const float* __restrict__ y,
                             const int* __restrict__ idx, float* __restrict__ out, int NT) {
    int warp = (blockIdx.x * blockDim.x + threadIdx.x) >> 5;
    int lane = threadIdx.x & 31;
    if (warp >= NT) return;
    int n = idx[warp];
    const float* p = h + (size_t)n * 512;
    float acc = 0.f;
#pragma unroll
    for (int c = lane; c < 512; c += 32) acc += p[c] * Wh[c];
#pragma unroll
    for (int o = 16; o; o >>= 1) acc += __shfl_xor_sync(0xffffffffu, acc, o);
    if (lane == 0) {
        float x = acc + bh[0];
        out[warp] = 1.f / (1.f + __expf(-x));
        out[NT + warp] = y[n];
    }
}

// ===========================================================================
extern "C" void kernel_launch(void* const* d_in, const int* in_sizes, int n_in,
                              void* d_out, int out_size) {
    const float* x     = (const float*)d_in[0];
    const int*   ei    = (const int*)d_in[1];
    const float* y     = (const float*)d_in[2];
    const int*   tidx  = (const int*)d_in[3];
    const float* bn0_g = (const float*)d_in[4];
    const float* bn0_b = (const float*)d_in[5];
    const float* W1l = (const float*)d_in[6],  *W1r = (const float*)d_in[7];
    const float* a1  = (const float*)d_in[8],  *b1  = (const float*)d_in[9];
    const float* bn1_g = (const float*)d_in[10], *bn1_b = (const float*)d_in[11];
    const float* W2l = (const float*)d_in[12], *W2r = (const float*)d_in[13];
    const float* a2  = (const float*)d_in[14], *b2  = (const float*)d_in[15];
    const float* bn2_g = (const float*)d_in[16], *bn2_b = (const float*)d_in[17];
    const float* W3l = (const float*)d_in[18], *W3r = (const float*)d_in[19];
    const float* a3  = (const float*)d_in[20], *b3  = (const float*)d_in[21];
    const float* bn3_g = (const float*)d_in[22], *bn3_b = (const float*)d_in[23];
    const float* W4l = (const float*)d_in[24], *W4r = (const float*)d_in[25];
    const float* a4  = (const float*)d_in[26], *b4  = (const float*)d_in[27];
    const float* Wh  = (const float*)d_in[28], *bh  = (const float*)d_in[29];

    const int Nn   = in_sizes[2];        // 8000
    const int FINv = in_sizes[0] / Nn;   // 3201
    const int E    = in_sizes[1] / 2;    // 64000
    const int Etot = E + Nn;
    const int NT   = in_sizes[3];

    float* buf = nullptr;
    cudaGetSymbolAddress((void**)&buf, g_buf);
    __nv_bfloat16* A1  = (__nv_bfloat16*)(buf + O_A1);
    __nv_bfloat16* A2  = (__nv_bfloat16*)(buf + O_A2);
    __nv_bfloat16* XL  = (__nv_bfloat16*)(buf + O_XL);
    __nv_bfloat16* XR  = (__nv_bfloat16*)(buf + O_XR);
    float* H1 = buf + O_H1;
    float* H2 = buf + O_H2;
    float* H3 = buf + O_H3;
    float* H4 = buf + O_H4;
    __nv_bfloat16* BT1 = (__nv_bfloat16*)(buf + O_BT1);
    __nv_bfloat16* BT2 = (__nv_bfloat16*)(buf + O_BT2);
    __nv_bfloat16* BT3 = (__nv_bfloat16*)(buf + O_BT3);
    __nv_bfloat16* BT4 = (__nv_bfloat16*)(buf + O_BT4);
    float* ST1 = buf + O_STAT;              // 2*3264
    float* ST2 = ST1 + 2 * 3264;            // 2*1024
    float* ST3 = ST2 + 2 * 1024;            // 2*512
    float* ST4 = ST3 + 2 * 512;             // 2*512
    int* CNT    = (int*)(buf + O_INT);
    int* ROWPTR = CNT + 8064;
    int* CSRSRC = ROWPTR + 8064;

    const int rows_per = (Nn + 31) / 32;
    const int GY = (Nn + BM - 1) / BM;

    cudaFuncSetAttribute(gemm_bf16_k, cudaFuncAttributeMaxDynamicSharedMemorySize, SMEM_GEMM);

    // ---- side stream + events (created once; capture-legal fork/join)
    static cudaStream_t s1 = nullptr;
    static cudaEvent_t ev_fork, ev_t1, ev_csr, ev_t2, ev_t3, ev_t4;
    if (s1 == nullptr) {
        cudaStreamCreateWithFlags(&s1, cudaStreamNonBlocking);
        cudaEventCreateWithFlags(&ev_fork, cudaEventDisableTiming);
        cudaEventCreateWithFlags(&ev_t1, cudaEventDisableTiming);
        cudaEventCreateWithFlags(&ev_csr, cudaEventDisableTiming);
        cudaEventCreateWithFlags(&ev_t2, cudaEventDisableTiming);
        cudaEventCreateWithFlags(&ev_t3, cudaEventDisableTiming);
        cudaEventCreateWithFlags(&ev_t4, cudaEventDisableTiming);
    }

    auto run_bn = [&](const float* in, int ldi, __nv_bfloat16* out, int ldo, int F,
                      float* ST, const float* g, const float* b, int relu) {
        dim3 grid((F + 255) / 256, 32);
        colstats_k<<<grid, 256>>>(in, ldi, Nn, F, rows_per, ST, ST + F);
        bn_apply_bf_k<<<2048, 256>>>(in, ldi, out, ldo, (long long)Nn * F, F, Nn,
                                     ST, ST + F, g, b, relu);
    };
    auto run_tr2_s1 = [&](const float* Wl, const float* Wr, __nv_bfloat16* BT,
                          int K, int Nc, int ldbt) {
        dim3 tg(Nc / 32, (K + 31) / 32, 2);
        transpose2_bf_k<<<tg, dim3(32, 8), 0, s1>>>(Wl, Wr, BT, (size_t)Nc * ldbt, K, Nc, ldbt);
    };

    // ---- fork side stream: all input-only prep work runs concurrently
    cudaEventRecord(ev_fork, 0);
    cudaStreamWaitEvent(s1, ev_fork, 0);
    run_tr2_s1(W1l, W1r, BT1, FINv, 1024, LDA0);
    cudaEventRecord(ev_t1, s1);
    hist_k<<<(Etot + 255) / 256, 256, 0, s1>>>(ei, E, Etot, CNT);
    scan8000_k<<<1, 1024, 0, s1>>>(CNT, ROWPTR, Nn);
    scatter_k<<<(Etot + 255) / 256, 256, 0, s1>>>(ei, E, Etot, ROWPTR, CNT, CSRSRC);
    cudaEventRecord(ev_csr, s1);
    run_tr2_s1(W2l, W2r, BT2, 1024, 512, 1024);
    cudaEventRecord(ev_t2, s1);
    run_tr2_s1(W3l, W3r, BT3, 512, 512, 512);
    cudaEventRecord(ev_t3, s1);
    run_tr2_s1(W4l, W4r, BT4, 512, 512, 512);
    cudaEventRecord(ev_t4, s1);

    // ---- main stream: layer 1
    run_bn(x, FINv, A1, LDA0, FINv, ST1, bn0_g, bn0_b, 0);
    cudaStreamWaitEvent(0, ev_t1, 0);
    gemm_bf16_k<<<dim3(2048 / BN, GY), 256, SMEM_GEMM>>>(A1, LDA0, BT1, LDA0, XL, XR, Nn, LDA0, 1024);
    cudaStreamWaitEvent(0, ev_csr, 0);
    node_warp_k<<<(Nn * 2 * 32 + 255) / 256, 256>>>(ROWPTR, CSRSRC, XL, XR, a1, b1, H1, 2, 0,
                                                    Nn * 2, ST1, 2 * 3264);

    // ---- layer 2
    run_bn(H1, 1024, A2, 1024, 1024, ST2, bn1_g, bn1_b, 1);
    cudaStreamWaitEvent(0, ev_t2, 0);
    gemm_bf16_k<<<dim3(1024 / BN, GY), 256, SMEM_GEMM>>>(A2, 1024, BT2, 1024, XL, XR, Nn, 1024, 512);
    node_warp_k<<<(Nn * 32 + 255) / 256, 256>>>(ROWPTR, CSRSRC, XL, XR, a2, b2, H2, 1, 0,
                                                Nn, ST2, 2 * 1024);

    // ---- layer 3
    run_bn(H2, 512, A2, 512, 512, ST3, bn2_g, bn2_b, 1);
    cudaStreamWaitEvent(0, ev_t3, 0);
    gemm_bf16_k<<<dim3(1024 / BN, GY), 256, SMEM_GEMM>>>(A2, 512, BT3, 512, XL, XR, Nn, 512, 512);
    node_warp_k<<<(Nn * 32 + 255) / 256, 256>>>(ROWPTR, CSRSRC, XL, XR, a3, b3, H3, 1, 0,
                                                Nn, ST3, 2 * 512);

    // ---- layer 4 (relu fused into edge stage)
    run_bn(H3, 512, A2, 512, 512, ST4, bn3_g, bn3_b, 1);
    cudaStreamWaitEvent(0, ev_t4, 0);
    gemm_bf16_k<<<dim3(1024 / BN, GY), 256, SMEM_GEMM>>>(A2, 512, BT4, 512, XL, XR, Nn, 512, 512);
    node_warp_k<<<(Nn * 32 + 255) / 256, 256>>>(ROWPTR, CSRSRC, XL, XR, a4, b4, H4, 1, 1,
                                                Nn, ST4, 2 * 512);

    // ---- fused head + gather (train indices only)
    headgather_k<<<(NT * 32 + 255) / 256, 256>>>(H4, Wh, bh, y, tidx, (float*)d_out, NT);
}

// round 15
// speedup vs baseline: 1.0794x; 1.0706x over previous
#include <cuda_runtime.h>
#include <cuda_bf16.h>
#include <cstdint>

// ===========================================================================
#define LDA0 3264            // 3201 padded to /64 (bf16 elems)

// float-offset layout (g_buf zero-initialized at load; pad regions never
// written -> statically zero across all calls)
#define O_A1   0ULL            // bf16 [8000*3264]
#define O_A2   13056000ULL     // bf16 [8000*1024] (also layers 3/4 with ld 512)
#define O_XL   17152000ULL     // f32 8000*1024
#define O_XR   25344000ULL     // f32 8000*1024
#define O_H1   33536000ULL     // f32 8000*1024
#define O_H2   41728000ULL     // f32 8000*512
#define O_H3   45824000ULL     // f32 8000*512
#define O_H4   49920000ULL     // f32 8000*512
#define O_BT1  54016000ULL     // bf16 2048*3264
#define O_BT2  57358336ULL     // bf16 1024*1024
#define O_BT3  57882624ULL     // bf16 1024*512
#define O_BT4  58144768ULL     // bf16 1024*512
#define O_STAT 58406912ULL     // per-layer SUM/SQ: L1 2*3264, L2 2*1024, L3/L4 2*512
#define O_INT  58427968ULL     // ints: CNT[8064], ROWPTR[8064], CSRSRC[72000]
__device__ float g_buf[58600000];

// ===========================================================================
// bf16 mma.sync GEMM, 2-stage cp.async pipeline + ldmatrix, 2 CTAs/SM.
// C[M, Ntot] = A[M,K] @ BT[Ntot,K]^T, fp32 accum, f32 output.
// Cols [0,HC) -> XL, [HC,2HC) -> XR. K%64==0, Ntot%128==0, HC%128==0.
#define BM 128
#define BN 128
#define BK 64
#define AST 72                       // bf16 row stride (64 data + 8 pad) = 144B
#define TILE_BH (BM * AST)
#define TILE_B  (TILE_BH * 2)        // 18432 B
#define NSTAGE 2
#define SMEM_GEMM (NSTAGE * 2 * TILE_B)   // 73728 B -> 2 CTAs/SM

#define LDSM_X4(r0, r1, r2, r3, addr) \
    asm volatile("ldmatrix.sync.aligned.m8n8.x4.shared.b16 {%0,%1,%2,%3}, [%4];" \
        : "=r"(r0), "=r"(r1), "=r"(r2), "=r"(r3) : "r"(addr))

#define CP_ASYNC16(dst, src, sz) \
    asm volatile("cp.async.cg.shared.global [%0], [%1], 16, %2;" \
        :: "r"(dst), "l"(src), "r"(sz))

__global__ __launch_bounds__(256, 2) void gemm_bf16_k(
    const __nv_bfloat16* __restrict__ A, int lda,
    const __nv_bfloat16* __restrict__ BT, int ldb,
    float* __restrict__ XL, float* __restrict__ XR,
    int M, int K, int HC)
{
    extern __shared__ __nv_bfloat16 smem[];
    const uint32_t smb = (uint32_t)__cvta_generic_to_shared(smem);
    int tid = threadIdx.x;
    int lane = tid & 31, wid = tid >> 5;
    int wm = wid & 3, wn = wid >> 2;      // warp grid 4(m) x 2(n), tile 32x64
    int m0 = blockIdx.y * BM, n0 = blockIdx.x * BN;

    // ldmatrix per-lane addressing
    int j = lane >> 3, sub = lane & 7;
    int mfrag = ((j & 1) << 3) + sub;     // A: m_block = j&1, k_block = j>>1
    int kfragA = (j >> 1) << 3;
    int nfrag = ((j >> 1) << 3) + sub;    // B: n_block = j>>1, k_block = j&1
    int kfragB = (j & 1) << 3;

    // cp.async per-thread addressing
    int row_ld = tid >> 3;                // 0..31
    int ch_ld = tid & 7;                  // 16B chunk 0..7

    float acc[2][8][4];
#pragma unroll
    for (int i = 0; i < 2; i++)
#pragma unroll
        for (int q = 0; q < 8; q++)
#pragma unroll
            for (int v = 0; v < 4; v++) acc[i][q][v] = 0.f;

    int ntiles = K / BK;

    auto load_stage = [&](int s, int k0) {
        uint32_t abase = smb + s * 2 * TILE_B;
        uint32_t bbase = abase + TILE_B;
#pragma unroll
        for (int i = 0; i < 4; i++) {
            int r = row_ld + i * 32;
            int m = m0 + r;
            const __nv_bfloat16* srcA =
                A + (size_t)(m < M ? m : 0) * lda + k0 + ch_ld * 8;
            uint32_t dstA = abase + (uint32_t)(r * AST + ch_ld * 8) * 2;
            CP_ASYNC16(dstA, srcA, (m < M) ? 16 : 0);
            const __nv_bfloat16* srcB = BT + (size_t)(n0 + r) * ldb + k0 + ch_ld * 8;
            uint32_t dstB = bbase + (uint32_t)(r * AST + ch_ld * 8) * 2;
            CP_ASYNC16(dstB, srcB, 16);
        }
        asm volatile("cp.async.commit_group;");
    };

    load_stage(0, 0);

    for (int t = 0; t < ntiles; t++) {
        if (t + 1 < ntiles) {
            load_stage((t + 1) & 1, (t + 1) * BK);
            asm volatile("cp.async.wait_group 1;");
        } else {
            asm volatile("cp.async.wait_group 0;");
        }
        __syncthreads();

        int s = t & 1;
        uint32_t abase = smb + s * 2 * TILE_B;
        uint32_t bbase = abase + TILE_B;
#pragma unroll
        for (int ks = 0; ks < 4; ks++) {
            uint32_t af[2][4];
#pragma unroll
            for (int mt = 0; mt < 2; mt++) {
                uint32_t addr = abase +
                    (uint32_t)((wm * 32 + mt * 16 + mfrag) * AST + ks * 16 + kfragA) * 2;
                LDSM_X4(af[mt][0], af[mt][1], af[mt][2], af[mt][3], addr);
            }
            uint32_t bf[8][2];
#pragma unroll
            for (int np = 0; np < 4; np++) {
                uint32_t r0, r1, r2, r3;
                uint32_t addr = bbase +
                    (uint32_t)((wn * 64 + np * 16 + nfrag) * AST + ks * 16 + kfragB) * 2;
                LDSM_X4(r0, r1, r2, r3, addr);
                bf[2 * np][0] = r0;     bf[2 * np][1] = r1;
                bf[2 * np + 1][0] = r2; bf[2 * np + 1][1] = r3;
            }
#pragma unroll
            for (int mt = 0; mt < 2; mt++)
#pragma unroll
                for (int nt = 0; nt < 8; nt++) {
                    asm volatile(
                        "mma.sync.aligned.m16n8k16.row.col.f32.bf16.bf16.f32 "
                        "{%0,%1,%2,%3}, {%4,%5,%6,%7}, {%8,%9}, {%0,%1,%2,%3};"
                        : "+f"(acc[mt][nt][0]), "+f"(acc[mt][nt][1]),
                          "+f"(acc[mt][nt][2]), "+f"(acc[mt][nt][3])
                        : "r"(af[mt][0]), "r"(af[mt][1]), "r"(af[mt][2]), "r"(af[mt][3]),
                          "r"(bf[nt][0]), "r"(bf[nt][1]));
                }
        }
        __syncthreads();
    }

    // epilogue (HC % 128 == 0 -> whole block in one of XL/XR)
    int g = lane >> 2, tq = lane & 3;
    float* Cout;
    int cbase;
    if (n0 < HC) { Cout = XL; cbase = n0; }
    else         { Cout = XR; cbase = n0 - HC; }
#pragma unroll
    for (int mt = 0; mt < 2; mt++) {
        int m = m0 + wm * 32 + mt * 16 + g;
#pragma unroll
        for (int nt = 0; nt < 8; nt++) {
            int c = cbase + wn * 64 + nt * 8 + 2 * tq;
            if (m < M)
                *(float2*)(Cout + (size_t)m * HC + c) = make_float2(acc[mt][nt][0], acc[mt][nt][1]);
            if (m + 8 < M)
                *(float2*)(Cout + (size_t)(m + 8) * HC + c) = make_float2(acc[mt][nt][2], acc[mt][nt][3]);
        }
    }
}

// ===========================================================================
// Fused dual weight transpose (fp32 -> bf16): z selects Wl/Wr.
__global__ void transpose2_bf_k(const float* __restrict__ W0, const float* __restrict__ W1,
                                __nv_bfloat16* __restrict__ WT, size_t halfoff,
                                int K, int Nc, int ldbt) {
    __shared__ float t[32][33];
    const float* W = blockIdx.z ? W1 : W0;
    __nv_bfloat16* dst = WT + (size_t)blockIdx.z * halfoff;
    int n0 = blockIdx.x * 32, k0 = blockIdx.y * 32;
#pragma unroll
    for (int i = 0; i < 32; i += 8) {
        int k = k0 + threadIdx.y + i, n = n0 + threadIdx.x;
        if (k < K && n < Nc) t[threadIdx.y + i][threadIdx.x] = W[(size_t)k * Nc + n];
    }
    __syncthreads();
#pragma unroll
    for (int i = 0; i < 32; i += 8) {
        int n = n0 + threadIdx.y + i, k = k0 + threadIdx.x;
        if (k < K && n < Nc) dst[(size_t)n * ldbt + k] = __float2bfloat16(t[threadIdx.x][threadIdx.y + i]);
    }
}

// ===========================================================================
// CSR build (edges + self loops, grouped by dst). CNT zero at entry;
// scatter drains it back to zero (self-cleaning, replay-safe).
__device__ __forceinline__ void edge_ep(const int* __restrict__ ei, int E, int e, int& s, int& d) {
    if (e < E) { s = ei[e]; d = ei[E + e]; }
    else       { s = e - E; d = e - E; }
}
__global__ void hist_k(const int* __restrict__ ei, int E, int Etot, int* __restrict__ cnt) {
    int i = blockIdx.x * blockDim.x + threadIdx.x;
    if (i >= Etot) return;
    int s, d; edge_ep(ei, E, i, s, d);
    atomicAdd(&cnt[d], 1);
}
__global__ void scan8000_k(const int* __restrict__ cnt, int* __restrict__ rowptr, int n) {
    __shared__ int sh[1024];
    int tid = threadIdx.x;
    int vals[8]; int s = 0;
#pragma unroll
    for (int q = 0; q < 8; q++) {
        int i = tid * 8 + q;
        vals[q] = (i < n) ? cnt[i] : 0;
        s += vals[q];
    }
    sh[tid] = s; __syncthreads();
    for (int off = 1; off < 1024; off <<= 1) {
        int v = (tid >= off) ? sh[tid - off] : 0;
        __syncthreads();
        sh[tid] += v;
        __syncthreads();
    }
    int run = sh[tid] - s;
#pragma unroll
    for (int q = 0; q < 8; q++) {
        int i = tid * 8 + q;
        if (i < n) rowptr[i] = run;
        run += vals[q];
    }
    if (tid == 1023) rowptr[n] = run;
}
__global__ void scatter_k(const int* __restrict__ ei, int E, int Etot,
                          const int* __restrict__ rowptr, int* __restrict__ cnt,
                          int* __restrict__ csr_src) {
    int i = blockIdx.x * blockDim.x + threadIdx.x;
    if (i >= Etot) return;
    int s, d; edge_ep(ei, E, i, s, d);
    int old = atomicAdd(&cnt[d], -1);        // drains cnt back to zero
    csr_src[rowptr[d] + old - 1] = s;
}

// ===========================================================================
// BatchNorm stats accumulate (SUM/SQ zero at entry; node_warp of this layer
// re-zeroes them after bn_apply has consumed them).
__global__ void colstats_k(const float* __restrict__ H, int ldi, int Nn, int F, int rows_per,
                           float* __restrict__ sum, float* __restrict__ sq) {
    int col = blockIdx.x * blockDim.x + threadIdx.x;
    if (col >= F) return;
    int r0 = blockIdx.y * rows_per;
    int r1 = min(r0 + rows_per, Nn);
    float s = 0.f, q = 0.f;
    for (int r = r0; r < r1; r++) {
        float v = H[(size_t)r * ldi + col];
        s += v; q += v * v;
    }
    atomicAdd(&sum[col], s);
    atomicAdd(&sq[col], q);
}
// BN apply with inline mean/rstd from SUM/SQ, writing packed bf16.
__global__ void bn_apply_bf_k(const float* __restrict__ X, int ldi,
                              __nv_bfloat16* __restrict__ O, int ldo,
                              long long total, int F, int Nn,
                              const float* __restrict__ sum, const float* __restrict__ sq,
                              const float* __restrict__ g, const float* __restrict__ b, int relu) {
    long long i = (long long)blockIdx.x * blockDim.x + threadIdx.x;
    long long st = (long long)gridDim.x * blockDim.x;
    float invN = 1.f / (float)Nn;
    for (; i < total; i += st) {
        int r = (int)(i / F), c = (int)(i % F);
        float m = sum[c] * invN;
        float var = sq[c] * invN - m * m;
        var = var > 0.f ? var : 0.f;
        float rs = rsqrtf(var + 1e-5f);
        float v = (X[(size_t)r * ldi + c] - m) * rs * g[c] + b[c];
        if (relu) v = fmaxf(v, 0.f);
        O[(size_t)r * ldo + c] = __float2bfloat16(v);
    }
}

// ===========================================================================
// Warp-per-(node,head) fused GATv2 edge stage: online segment softmax +
// weighted aggregation + mean + bias (+relu), all in registers, no syncs.
// Block 0 additionally zeroes this layer's SUM/SQ (runs after bn_apply).
__global__ __launch_bounds__(256) void node_warp_k(
    const int* __restrict__ rowptr, const int* __restrict__ csr_src,
    const float* __restrict__ xl, const float* __restrict__ xr,
    const float* __restrict__ att, const float* __restrict__ bias,
    float* __restrict__ out, int H, int relu, int NH,
    float* __restrict__ cln, int cln_n)
{
    if (blockIdx.x == 0) {
        for (int i = threadIdx.x; i < cln_n; i += blockDim.x) cln[i] = 0.f;
    }
    int w = (blockIdx.x * blockDim.x + threadIdx.x) >> 5;
    int lane = threadIdx.x & 31;
    if (w >= NH) return;
    int n = w / H, h = w - n * H;
    size_t base = (size_t)w * 512;          // == (n*H + h)*512

    float4 xr4[4], at4[4];
#pragma unroll
    for (int g = 0; g < 4; g++) {
        xr4[g] = *(const float4*)(xr + base + lane * 4 + g * 128);
        at4[g] = *(const float4*)(att + (size_t)h * 512 + lane * 4 + g * 128);
    }

    int r0 = rowptr[n], r1 = rowptr[n + 1];
    float m = -3.4e38f, d = 0.f;
    float4 acc4[4];
#pragma unroll
    for (int g = 0; g < 4; g++) acc4[g] = make_float4(0.f, 0.f, 0.f, 0.f);

    float4 l4[4];
    {
        size_t sb = ((size_t)csr_src[r0] * H + h) * 512;
#pragma unroll
        for (int g = 0; g < 4; g++) l4[g] = *(const float4*)(xl + sb + lane * 4 + g * 128);
    }

    for (int i = r0; i < r1; i++) {
        // unconditional clamped prefetch (no branch, loads always valid)
        int nx = i + 1 < r1 ? i + 1 : i;
        size_t sb = ((size_t)csr_src[nx] * H + h) * 512;
        float4 nl4[4];
#pragma unroll
        for (int g = 0; g < 4; g++) nl4[g] = *(const float4*)(xl + sb + lane * 4 + g * 128);

        float part = 0.f;
#pragma unroll
        for (int g = 0; g < 4; g++) {
            float z;
            z = l4[g].x + xr4[g].x; z = z > 0.f ? z : 0.2f * z; part += at4[g].x * z;
            z = l4[g].y + xr4[g].y; z = z > 0.f ? z : 0.2f * z; part += at4[g].y * z;
            z = l4[g].z + xr4[g].z; z = z > 0.f ? z : 0.2f * z; part += at4[g].z * z;
            z = l4[g].w + xr4[g].w; z = z > 0.f ? z : 0.2f * z; part += at4[g].w * z;
        }
#pragma unroll
        for (int o = 16; o; o >>= 1) part += __shfl_xor_sync(0xffffffffu, part, o);
        float mn = fmaxf(m, part);
        float f = __expf(m - mn), e = __expf(part - mn);
        d = d * f + e;
#pragma unroll
        for (int g = 0; g < 4; g++) {
            acc4[g].x = acc4[g].x * f + e * l4[g].x;
            acc4[g].y = acc4[g].y * f + e * l4[g].y;
            acc4[g].z = acc4[g].z * f + e * l4[g].z;
            acc4[g].w = acc4[g].w * f + e * l4[g].w;
        }
        m = mn;
#pragma unroll
        for (int g = 0; g < 4; g++) l4[g] = nl4[g];
    }
    float inv = 1.f / (d * (float)(r1 - r0));
#pragma unroll
    for (int g = 0; g < 4; g++) {
        float4 bv = *(const float4*)(bias + (size_t)h * 512 + lane * 4 + g * 128);
        float4 o4;
        o4.x = acc4[g].x * inv + bv.x;
        o4.y = acc4[g].y * inv + bv.y;
        o4.z = acc4[g].z * inv + bv.z;
        o4.w = acc4[g].w * inv + bv.w;
        if (relu) {
            o4.x = fmaxf(o4.x, 0.f); o4.y = fmaxf(o4.y, 0.f);
            o4.z = fmaxf(o4.z, 0.f); o4.w = fmaxf(o4.w, 0.f);
        }
        *(float4*)(out + base + lane * 4 + g * 128) = o4;
    }
}

// ===========================================================================
// Fused head + gather: evaluate sigmoid head only at train indices.
__global__ void headgather_k(const float* __restrict__ h, const float* __restrict__ Wh,
                             const float* __restrict__ bh, const float* __restrict__ y,
                             const int* __restrict__ idx, float* __restrict__ out, int NT) {
    int warp = (blockIdx.x * blockDim.x + threadIdx.x) >> 5;
    int lane = threadIdx.x & 31;
    if (warp >= NT) return;
    int n = idx[warp];
    const float* p = h + (size_t)n * 512;
    float acc = 0.f;
#pragma unroll
    for (int c = lane; c < 512; c += 32) acc += p[c] * Wh[c];
#pragma unroll
    for (int o = 16; o; o >>= 1) acc += __shfl_xor_sync(0xffffffffu, acc, o);
    if (lane == 0) {
        float x = acc + bh[0];
        out[warp] = 1.f / (1.f + __expf(-x));
        out[NT + warp] = y[n];
    }
}

// ===========================================================================
extern "C" void kernel_launch(void* const* d_in, const int* in_sizes, int n_in,
                              void* d_out, int out_size) {
    const float* x     = (const float*)d_in[0];
    const int*   ei    = (const int*)d_in[1];
    const float* y     = (const float*)d_in[2];
    const int*   tidx  = (const int*)d_in[3];
    const float* bn0_g = (const float*)d_in[4];
    const float* bn0_b = (const float*)d_in[5];
    const float* W1l = (const float*)d_in[6],  *W1r = (const float*)d_in[7];
    const float* a1  = (const float*)d_in[8],  *b1  = (const float*)d_in[9];
    const float* bn1_g = (const float*)d_in[10], *bn1_b = (const float*)d_in[11];
    const float* W2l = (const float*)d_in[12], *W2r = (const float*)d_in[13];
    const float* a2  = (const float*)d_in[14], *b2  = (const float*)d_in[15];
    const float* bn2_g = (const float*)d_in[16], *bn2_b = (const float*)d_in[17];
    const float* W3l = (const float*)d_in[18], *W3r = (const float*)d_in[19];
    const float* a3  = (const float*)d_in[20], *b3  = (const float*)d_in[21];
    const float* bn3_g = (const float*)d_in[22], *bn3_b = (const float*)d_in[23];
    const float* W4l = (const float*)d_in[24], *W4r = (const float*)d_in[25];
    const float* a4  = (const float*)d_in[26], *b4  = (const float*)d_in[27];
    const float* Wh  = (const float*)d_in[28], *bh  = (const float*)d_in[29];

    const int Nn   = in_sizes[2];        // 8000
    const int FINv = in_sizes[0] / Nn;   // 3201
    const int E    = in_sizes[1] / 2;    // 64000
    const int Etot = E + Nn;
    const int NT   = in_sizes[3];

    float* buf = nullptr;
    cudaGetSymbolAddress((void**)&buf, g_buf);
    __nv_bfloat16* A1  = (__nv_bfloat16*)(buf + O_A1);
    __nv_bfloat16* A2  = (__nv_bfloat16*)(buf + O_A2);
    float* XL = buf + O_XL;
    float* XR = buf + O_XR;
    float* H1 = buf + O_H1;
    float* H2 = buf + O_H2;
    float* H3 = buf + O_H3;
    float* H4 = buf + O_H4;
    __nv_bfloat16* BT1 = (__nv_bfloat16*)(buf + O_BT1);
    __nv_bfloat16* BT2 = (__nv_bfloat16*)(buf + O_BT2);
    __nv_bfloat16* BT3 = (__nv_bfloat16*)(buf + O_BT3);
    __nv_bfloat16* BT4 = (__nv_bfloat16*)(buf + O_BT4);
    float* ST1 = buf + O_STAT;              // 2*3264
    float* ST2 = ST1 + 2 * 3264;            // 2*1024
    float* ST3 = ST2 + 2 * 1024;            // 2*512
    float* ST4 = ST3 + 2 * 512;             // 2*512
    int* CNT    = (int*)(buf + O_INT);
    int* ROWPTR = CNT + 8064;
    int* CSRSRC = ROWPTR + 8064;

    const int rows_per = (Nn + 63) / 64;    // 64 row-blocks (was 32)
    const int GY = (Nn + BM - 1) / BM;

    cudaFuncSetAttribute(gemm_bf16_k, cudaFuncAttributeMaxDynamicSharedMemorySize, SMEM_GEMM);

    // ---- side stream + events (created once; capture-legal fork/join)
    static cudaStream_t s1 = nullptr;
    static cudaEvent_t ev_fork, ev_t1, ev_csr, ev_t2, ev_t3, ev_t4;
    if (s1 == nullptr) {
        cudaStreamCreateWithFlags(&s1, cudaStreamNonBlocking);
        cudaEventCreateWithFlags(&ev_fork, cudaEventDisableTiming);
        cudaEventCreateWithFlags(&ev_t1, cudaEventDisableTiming);
        cudaEventCreateWithFlags(&ev_csr, cudaEventDisableTiming);
        cudaEventCreateWithFlags(&ev_t2, cudaEventDisableTiming);
        cudaEventCreateWithFlags(&ev_t3, cudaEventDisableTiming);
        cudaEventCreateWithFlags(&ev_t4, cudaEventDisableTiming);
    }

    auto run_bn = [&](const float* in, int ldi, __nv_bfloat16* out, int ldo, int F,
                      float* ST, const float* g, const float* b, int relu) {
        dim3 grid((F + 255) / 256, 64);
        colstats_k<<<grid, 256>>>(in, ldi, Nn, F, rows_per, ST, ST + F);
        bn_apply_bf_k<<<2048, 256>>>(in, ldi, out, ldo, (long long)Nn * F, F, Nn,
                                     ST, ST + F, g, b, relu);
    };
    auto run_tr2_s1 = [&](const float* Wl, const float* Wr, __nv_bfloat16* BT,
                          int K, int Nc, int ldbt) {
        dim3 tg(Nc / 32, (K + 31) / 32, 2);
        transpose2_bf_k<<<tg, dim3(32, 8), 0, s1>>>(Wl, Wr, BT, (size_t)Nc * ldbt, K, Nc, ldbt);
    };

    // ---- fork side stream: all input-only prep work runs concurrently
    cudaEventRecord(ev_fork, 0);
    cudaStreamWaitEvent(s1, ev_fork, 0);
    run_tr2_s1(W1l, W1r, BT1, FINv, 1024, LDA0);
    cudaEventRecord(ev_t1, s1);
    hist_k<<<(Etot + 255) / 256, 256, 0, s1>>>(ei, E, Etot, CNT);
    scan8000_k<<<1, 1024, 0, s1>>>(CNT, ROWPTR, Nn);
    scatter_k<<<(Etot + 255) / 256, 256, 0, s1>>>(ei, E, Etot, ROWPTR, CNT, CSRSRC);
    cudaEventRecord(ev_csr, s1);
    run_tr2_s1(W2l, W2r, BT2, 1024, 512, 1024);
    cudaEventRecord(ev_t2, s1);
    run_tr2_s1(W3l, W3r, BT3, 512, 512, 512);
    cudaEventRecord(ev_t3, s1);
    run_tr2_s1(W4l, W4r, BT4, 512, 512, 512);
    cudaEventRecord(ev_t4, s1);

    // ---- main stream: layer 1
    run_bn(x, FINv, A1, LDA0, FINv, ST1, bn0_g, bn0_b, 0);
    cudaStreamWaitEvent(0, ev_t1, 0);
    gemm_bf16_k<<<dim3(2048 / BN, GY), 256, SMEM_GEMM>>>(A1, LDA0, BT1, LDA0, XL, XR, Nn, LDA0, 1024);
    cudaStreamWaitEvent(0, ev_csr, 0);
    node_warp_k<<<(Nn * 2 * 32 + 255) / 256, 256>>>(ROWPTR, CSRSRC, XL, XR, a1, b1, H1, 2, 0,
                                                    Nn * 2, ST1, 2 * 3264);

    // ---- layer 2
    run_bn(H1, 1024, A2, 1024, 1024, ST2, bn1_g, bn1_b, 1);
    cudaStreamWaitEvent(0, ev_t2, 0);
    gemm_bf16_k<<<dim3(1024 / BN, GY), 256, SMEM_GEMM>>>(A2, 1024, BT2, 1024, XL, XR, Nn, 1024, 512);
    node_warp_k<<<(Nn * 32 + 255) / 256, 256>>>(ROWPTR, CSRSRC, XL, XR, a2, b2, H2, 1, 0,
                                                Nn, ST2, 2 * 1024);

    // ---- layer 3
    run_bn(H2, 512, A2, 512, 512, ST3, bn2_g, bn2_b, 1);
    cudaStreamWaitEvent(0, ev_t3, 0);
    gemm_bf16_k<<<dim3(1024 / BN, GY), 256, SMEM_GEMM>>>(A2, 512, BT3, 512, XL, XR, Nn, 512, 512);
    node_warp_k<<<(Nn * 32 + 255) / 256, 256>>>(ROWPTR, CSRSRC, XL, XR, a3, b3, H3, 1, 0,
                                                Nn, ST3, 2 * 512);

    // ---- layer 4 (relu fused into edge stage)
    run_bn(H3, 512, A2, 512, 512, ST4, bn3_g, bn3_b, 1);
    cudaStreamWaitEvent(0, ev_t4, 0);
    gemm_bf16_k<<<dim3(1024 / BN, GY), 256, SMEM_GEMM>>>(A2, 512, BT4, 512, XL, XR, Nn, 512, 512);
    node_warp_k<<<(Nn * 32 + 255) / 256, 256>>>(ROWPTR, CSRSRC, XL, XR, a4, b4, H4, 1, 1,
                                                Nn, ST4, 2 * 512);

    // ---- fused head + gather (train indices only)
    headgather_k<<<(NT * 32 + 255) / 256, 256>>>(H4, Wh, bh, y, tidx, (float*)d_out, NT);
}